// round 3
// baseline (speedup 1.0000x reference)
#include <cuda_runtime.h>
#include <math.h>

#define K_CB 196560
#define EMB 24
#define TT 16

// ---------------- device scratch (static allocation only) ----------------
__device__ float g_res[12288];                 // residual [2][24][16][16]
__device__ float g_rdown[512 * EMB];           // downsampled tokens [N][24]
__device__ float g_zq[512 * EMB];              // quantized tokens (post-STE)
__device__ unsigned long long g_best[512];     // packed (orderable sim, ~idx)
__device__ float g_wd[10][16][16];             // down weights [s][inY][outy]
__device__ float g_wu[10][16][16];             // up   weights [s][iny][outY]

// ---------------- helpers ----------------
__device__ __forceinline__ unsigned int forder(float f) {
    unsigned int u = __float_as_uint(f);
    return (u & 0x80000000u) ? ~u : (u | 0x80000000u);
}

__device__ __forceinline__ unsigned long long ffma2(unsigned long long a,
                                                    unsigned long long b,
                                                    unsigned long long c) {
    unsigned long long d;
    asm("fma.rn.f32x2 %0, %1, %2, %3;" : "=l"(d) : "l"(a), "l"(b), "l"(c));
    return d;
}
__device__ __forceinline__ unsigned long long packf2(float lo, float hi) {
    unsigned long long r;
    asm("mov.b64 %0, {%1, %2};" : "=l"(r) : "f"(lo), "f"(hi));
    return r;
}
__device__ __forceinline__ float2 unpackf2(unsigned long long v) {
    float lo, hi;
    asm("mov.b64 {%0, %1}, %2;" : "=f"(lo), "=f"(hi) : "l"(v));
    return make_float2(lo, hi);
}

// Replicates jax.image.resize compute_weight_mat (triangle kernel,
// antialias=True, translation=0) for one output column o.
__device__ void compute_col(int in_size, int out_size, int o, float* wcol) {
    float inv_scale = (float)((double)in_size / (double)out_size);
    float kscale = fmaxf(inv_scale, 1.0f);
    float sample_f = ((float)o + 0.5f) * inv_scale - 0.5f;
    float total = 0.0f;
    for (int i = 0; i < in_size; ++i) {
        float x = fabsf(sample_f - (float)i) / kscale;
        float w = fmaxf(0.0f, 1.0f - x);
        wcol[i] = w;
        total += w;
    }
    bool ok = fabsf(total) > 1000.0f * 1.1920928955078125e-7f;
    float denom = (total != 0.0f) ? total : 1.0f;
    bool inr = (sample_f >= -0.5f) && (sample_f <= (float)in_size - 0.5f);
    for (int i = 0; i < in_size; ++i) {
        float w = ok ? (wcol[i] / denom) : 0.0f;
        wcol[i] = inr ? w : 0.0f;
    }
}

// ---------------- init: residual copy, zero z_hat, build weight mats ------
__global__ void init_kernel(const float* __restrict__ z, float* __restrict__ out) {
    int tid = threadIdx.x;
    for (int i = tid; i < 12288; i += blockDim.x) {
        g_res[i] = z[i];
        out[i] = 0.0f;
    }
    const int hs9[9] = {1, 2, 3, 4, 5, 6, 8, 10, 13};
    // 52 down-columns + 9*16 up-columns = 196 tasks
    for (int task = tid; task < 52 + 144; task += blockDim.x) {
        float wcol[16];
        if (task < 52) {
            int rem = task, s = 0;
            while (rem >= hs9[s]) { rem -= hs9[s]; s++; }
            compute_col(16, hs9[s], rem, wcol);
            for (int i = 0; i < 16; i++) g_wd[s][i][rem] = wcol[i];
        } else {
            int r = task - 52;
            int s = r / 16, o = r % 16;
            compute_col(hs9[s], 16, o, wcol);
            for (int i = 0; i < 16; i++) g_wu[s][i][o] = (i < hs9[s]) ? wcol[i] : 0.0f;
        }
    }
}

// ---------------- downsample residual -> tokens (separable H then W) ------
__global__ void downsample_kernel(int s, int h, int N) {
    __shared__ float tile[16][16];
    __shared__ float tmp[16][16];
    int blk = blockIdx.x;        // b*24 + d
    int tid = threadIdx.x;
    tile[tid >> 4][tid & 15] = g_res[blk * 256 + tid];
    if (blk == 0) {
        for (int n = tid; n < N; n += 256) g_best[n] = 0ull;
    }
    __syncthreads();
    int b = blk / 24, d = blk % 24;
    if (h == 16) {  // jax resize skips equal dims -> identity
        g_rdown[(b * 256 + tid) * EMB + d] = tile[tid >> 4][tid & 15];
        return;
    }
    if (tid < h * 16) {
        int y = tid / 16, X = tid % 16;
        float acc = 0.0f;
        for (int Y = 0; Y < 16; Y++) acc += g_wd[s][Y][y] * tile[Y][X];
        tmp[y][X] = acc;
    }
    __syncthreads();
    if (tid < h * h) {
        int y = tid / h, x = tid % h;
        float acc = 0.0f;
        for (int X = 0; X < 16; X++) acc += g_wd[s][X][x] * tmp[y][X];
        g_rdown[(b * h * h + tid) * EMB + d] = acc;
    }
}

// ---------------- the heavy scan: argmax over 196560 codewords ------------
__global__ void __launch_bounds__(256) scan_kernel(const float* __restrict__ cb,
                                                   int N, int rows_per_block) {
    __shared__ __align__(16) float tok[TT][24];
    __shared__ unsigned long long wred[8][TT];
    int tid = threadIdx.x;
    int token0 = blockIdx.y * TT;
    for (int i = tid; i < TT * 24; i += 256) {
        int t = i / 24, d = i % 24;
        int tk = token0 + t;
        tok[t][d] = (tk < N) ? g_rdown[tk * EMB + d] : 0.0f;
    }
    __syncthreads();

    float bestv[TT];
    int besti[TT];
#pragma unroll
    for (int t = 0; t < TT; t++) { bestv[t] = -3.4e38f; besti[t] = 0; }

    int rbeg = blockIdx.x * rows_per_block;
    int rend = min(K_CB, rbeg + rows_per_block);
    const float4* __restrict__ cbv = (const float4*)cb;

    for (int r = rbeg + tid; r < rend; r += 256) {
        float4 c0 = __ldg(&cbv[r * 6 + 0]);
        float4 c1 = __ldg(&cbv[r * 6 + 1]);
        float4 c2 = __ldg(&cbv[r * 6 + 2]);
        float4 c3 = __ldg(&cbv[r * 6 + 3]);
        float4 c4 = __ldg(&cbv[r * 6 + 4]);
        float4 c5 = __ldg(&cbv[r * 6 + 5]);
        unsigned long long cp[12];
        cp[0]  = packf2(c0.x, c0.y); cp[1]  = packf2(c0.z, c0.w);
        cp[2]  = packf2(c1.x, c1.y); cp[3]  = packf2(c1.z, c1.w);
        cp[4]  = packf2(c2.x, c2.y); cp[5]  = packf2(c2.z, c2.w);
        cp[6]  = packf2(c3.x, c3.y); cp[7]  = packf2(c3.z, c3.w);
        cp[8]  = packf2(c4.x, c4.y); cp[9]  = packf2(c4.z, c4.w);
        cp[10] = packf2(c5.x, c5.y); cp[11] = packf2(c5.z, c5.w);
#pragma unroll
        for (int t = 0; t < TT; t++) {
            const ulonglong2* tz = (const ulonglong2*)tok[t];
            ulonglong2 z0 = tz[0], z1 = tz[1], z2 = tz[2];
            unsigned long long acc = ffma2(cp[0], z0.x, 0ull);
            acc = ffma2(cp[1], z0.y, acc);
            acc = ffma2(cp[2], z1.x, acc);
            acc = ffma2(cp[3], z1.y, acc);
            acc = ffma2(cp[4], z2.x, acc);
            acc = ffma2(cp[5], z2.y, acc);
            ulonglong2 z3 = tz[3], z4 = tz[4], z5 = tz[5];
            acc = ffma2(cp[6], z3.x, acc);
            acc = ffma2(cp[7], z3.y, acc);
            acc = ffma2(cp[8], z4.x, acc);
            acc = ffma2(cp[9], z4.y, acc);
            acc = ffma2(cp[10], z5.x, acc);
            acc = ffma2(cp[11], z5.y, acc);
            float2 s2 = unpackf2(acc);
            float sim = s2.x + s2.y;
            if (sim > bestv[t]) { bestv[t] = sim; besti[t] = r; }
        }
    }

    unsigned long long p[TT];
#pragma unroll
    for (int t = 0; t < TT; t++)
        p[t] = ((unsigned long long)forder(bestv[t]) << 32) |
               (unsigned long long)((unsigned)~besti[t]);
#pragma unroll
    for (int t = 0; t < TT; t++) {
#pragma unroll
        for (int off = 16; off; off >>= 1) {
            unsigned long long o = __shfl_down_sync(0xFFFFFFFFu, p[t], off);
            if (o > p[t]) p[t] = o;
        }
    }
    int warp = tid >> 5, lane = tid & 31;
    if (lane == 0) {
#pragma unroll
        for (int t = 0; t < TT; t++) wred[warp][t] = p[t];
    }
    __syncthreads();
    if (tid < TT) {
        unsigned long long m = wred[0][tid];
#pragma unroll
        for (int w = 1; w < 8; w++) {
            unsigned long long v = wred[w][tid];
            if (v > m) m = v;
        }
        if (token0 + tid < N) atomicMax(&g_best[token0 + tid], m);
    }
}

// ---------------- gather + renorm + STE, emit index ----------------------
__global__ void finalize_kernel(const float* __restrict__ cb, int N,
                                float* __restrict__ out, int idx_off) {
    int n = blockIdx.x * blockDim.x + threadIdx.x;
    if (n >= N) return;
    unsigned long long p = g_best[n];
    unsigned row = ~((unsigned)(p & 0xFFFFFFFFull));
    out[idx_off + n] = (float)row;
    const float* c = cb + (size_t)row * EMB;
    float ss = 0.0f;
    for (int d = 0; d < EMB; d++) { float v = c[d]; ss += v * v; }
    float nrm = sqrtf(ss);
    for (int d = 0; d < EMB; d++) {
        float q = c[d] / nrm;
        float zf = g_rdown[n * EMB + d];
        g_zq[n * EMB + d] = zf + (q - zf);   // STE forward rounding, ulp-exact
    }
}

// ---------------- upsample + accumulate z_hat, subtract residual ---------
__global__ void upsample_kernel(int s, int h, float* __restrict__ zhat) {
    __shared__ float zt[16][16];
    __shared__ float tmp[16][16];
    int blk = blockIdx.x, tid = threadIdx.x;
    int b = blk / 24, d = blk % 24;
    if (tid < h * h) zt[tid / h][tid % h] = g_zq[(b * h * h + tid) * EMB + d];
    __syncthreads();
    float up;
    if (h == 16) {
        up = zt[tid >> 4][tid & 15];
    } else {
        if (tid < 16 * h) {
            int Y = tid / h, x = tid % h;
            float acc = 0.0f;
            for (int y = 0; y < h; y++) acc += g_wu[s][y][Y] * zt[y][x];
            tmp[Y][x] = acc;
        }
        __syncthreads();
        int Y = tid >> 4, X = tid & 15;
        float acc = 0.0f;
        for (int x = 0; x < h; x++) acc += g_wu[s][x][X] * tmp[Y][x];
        up = acc;
    }
    int g = blk * 256 + tid;
    zhat[g] += up;
    g_res[g] -= up;
}

// ---------------- launch ---------------------------------------------------
extern "C" void kernel_launch(void* const* d_in, const int* in_sizes, int n_in,
                              void* d_out, int out_size) {
    const float* z;
    const float* cb;
    if (in_sizes[0] == 12288) {
        z = (const float*)d_in[0];
        cb = (const float*)d_in[1];
    } else {
        z = (const float*)d_in[1];
        cb = (const float*)d_in[0];
    }
    float* out = (float*)d_out;

    init_kernel<<<1, 256>>>(z, out);

    static const int hs[10] = {1, 2, 3, 4, 5, 6, 8, 10, 13, 16};
    int off = 12288;
    for (int s = 0; s < 10; s++) {
        int h = hs[s];
        int N = 2 * h * h;
        downsample_kernel<<<48, 256>>>(s, h, N);
        int tiles = (N + TT - 1) / TT;
        int gx = 2048 / tiles;
        if (gx > 768) gx = 768;
        if (gx < 1) gx = 1;
        int rpb = (K_CB + gx - 1) / gx;
        scan_kernel<<<dim3(gx, tiles), 256>>>(cb, N, rpb);
        finalize_kernel<<<(N + 127) / 128, 128>>>(cb, N, out, off);
        upsample_kernel<<<48, 256>>>(s, h, out);
        off += N;
    }
}

// round 4
// speedup vs baseline: 1.0031x; 1.0031x over previous
#include <cuda_runtime.h>
#include <math.h>

#define K_CB 196560
#define EMB 24
#define TT 16

// ---------------- device scratch (static allocation only) ----------------
__device__ float g_res[12288];                 // residual [2][24][16][16]
__device__ float g_rdown[512 * EMB];           // downsampled tokens [N][24]
__device__ float g_zq[512 * EMB];              // quantized tokens (post-STE)
__device__ unsigned long long g_best[512];     // packed (orderable sim, ~idx)
__device__ float g_wd[10][16][16];             // down weights [s][inY][outy]
__device__ float g_wu[10][16][16];             // up   weights [s][iny][outY]

// ---------------- helpers ----------------
__device__ __forceinline__ unsigned int forder(float f) {
    unsigned int u = __float_as_uint(f);
    return (u & 0x80000000u) ? ~u : (u | 0x80000000u);
}

__device__ __forceinline__ unsigned long long ffma2(unsigned long long a,
                                                    unsigned long long b,
                                                    unsigned long long c) {
    unsigned long long d;
    asm("fma.rn.f32x2 %0, %1, %2, %3;" : "=l"(d) : "l"(a), "l"(b), "l"(c));
    return d;
}
__device__ __forceinline__ unsigned long long packf2(float lo, float hi) {
    unsigned long long r;
    asm("mov.b64 %0, {%1, %2};" : "=l"(r) : "f"(lo), "f"(hi));
    return r;
}
__device__ __forceinline__ float2 unpackf2(unsigned long long v) {
    float lo, hi;
    asm("mov.b64 {%0, %1}, %2;" : "=f"(lo), "=f"(hi) : "l"(v));
    return make_float2(lo, hi);
}

// Replicates jax.image.resize compute_weight_mat (triangle kernel,
// antialias=True, translation=0) for one output column o.
__device__ void compute_col(int in_size, int out_size, int o, float* wcol) {
    float inv_scale = (float)((double)in_size / (double)out_size);
    float kscale = fmaxf(inv_scale, 1.0f);
    float sample_f = ((float)o + 0.5f) * inv_scale - 0.5f;
    float total = 0.0f;
    for (int i = 0; i < in_size; ++i) {
        float x = fabsf(sample_f - (float)i) / kscale;
        float w = fmaxf(0.0f, 1.0f - x);
        wcol[i] = w;
        total += w;
    }
    bool ok = fabsf(total) > 1000.0f * 1.1920928955078125e-7f;
    float denom = (total != 0.0f) ? total : 1.0f;
    bool inr = (sample_f >= -0.5f) && (sample_f <= (float)in_size - 0.5f);
    for (int i = 0; i < in_size; ++i) {
        float w = ok ? (wcol[i] / denom) : 0.0f;
        wcol[i] = inr ? w : 0.0f;
    }
}

// ---------------- init: residual copy, zero z_hat, build weight mats ------
__global__ void init_kernel(const float* __restrict__ z, float* __restrict__ out) {
    int tid = threadIdx.x;
    for (int i = tid; i < 12288; i += blockDim.x) {
        g_res[i] = z[i];
        out[i] = 0.0f;
    }
    const int hs9[9] = {1, 2, 3, 4, 5, 6, 8, 10, 13};
    // 52 down-columns + 9*16 up-columns = 196 tasks
    for (int task = tid; task < 52 + 144; task += blockDim.x) {
        float wcol[16];
        if (task < 52) {
            int rem = task, s = 0;
            while (rem >= hs9[s]) { rem -= hs9[s]; s++; }
            compute_col(16, hs9[s], rem, wcol);
            for (int i = 0; i < 16; i++) g_wd[s][i][rem] = wcol[i];
        } else {
            int r = task - 52;
            int s = r / 16, o = r % 16;
            compute_col(hs9[s], 16, o, wcol);
            for (int i = 0; i < 16; i++) g_wu[s][i][o] = (i < hs9[s]) ? wcol[i] : 0.0f;
        }
    }
}

// ---------------- downsample residual -> tokens (separable H then W) ------
__global__ void downsample_kernel(int s, int h, int N) {
    __shared__ float tile[16][16];
    __shared__ float tmp[16][16];
    int blk = blockIdx.x;        // b*24 + d
    int tid = threadIdx.x;
    tile[tid >> 4][tid & 15] = g_res[blk * 256 + tid];
    if (blk == 0) {
        for (int n = tid; n < N; n += 256) g_best[n] = 0ull;
    }
    __syncthreads();
    int b = blk / 24, d = blk % 24;
    if (h == 16) {  // jax resize skips equal dims -> identity
        g_rdown[(b * 256 + tid) * EMB + d] = tile[tid >> 4][tid & 15];
        return;
    }
    if (tid < h * 16) {
        int y = tid / 16, X = tid % 16;
        float acc = 0.0f;
        for (int Y = 0; Y < 16; Y++) acc += g_wd[s][Y][y] * tile[Y][X];
        tmp[y][X] = acc;
    }
    __syncthreads();
    if (tid < h * h) {
        int y = tid / h, x = tid % h;
        float acc = 0.0f;
        for (int X = 0; X < 16; X++) acc += g_wd[s][X][x] * tmp[y][X];
        g_rdown[(b * h * h + tid) * EMB + d] = acc;
    }
}

// ---------------- the heavy scan: argmax over 196560 codewords ------------
__global__ void __launch_bounds__(256) scan_kernel(const float* __restrict__ cb,
                                                   int N, int rows_per_block) {
    __shared__ __align__(16) float tok[TT][24];
    __shared__ unsigned long long wred[8][TT];
    int tid = threadIdx.x;
    int token0 = blockIdx.y * TT;
    for (int i = tid; i < TT * 24; i += 256) {
        int t = i / 24, d = i % 24;
        int tk = token0 + t;
        tok[t][d] = (tk < N) ? g_rdown[tk * EMB + d] : 0.0f;
    }
    __syncthreads();

    float bestv[TT];
    int besti[TT];
#pragma unroll
    for (int t = 0; t < TT; t++) { bestv[t] = -3.4e38f; besti[t] = 0; }

    int rbeg = blockIdx.x * rows_per_block;
    int rend = min(K_CB, rbeg + rows_per_block);
    const float4* __restrict__ cbv = (const float4*)cb;

    for (int r = rbeg + tid; r < rend; r += 256) {
        float4 c0 = __ldg(&cbv[r * 6 + 0]);
        float4 c1 = __ldg(&cbv[r * 6 + 1]);
        float4 c2 = __ldg(&cbv[r * 6 + 2]);
        float4 c3 = __ldg(&cbv[r * 6 + 3]);
        float4 c4 = __ldg(&cbv[r * 6 + 4]);
        float4 c5 = __ldg(&cbv[r * 6 + 5]);
        unsigned long long cp[12];
        cp[0]  = packf2(c0.x, c0.y); cp[1]  = packf2(c0.z, c0.w);
        cp[2]  = packf2(c1.x, c1.y); cp[3]  = packf2(c1.z, c1.w);
        cp[4]  = packf2(c2.x, c2.y); cp[5]  = packf2(c2.z, c2.w);
        cp[6]  = packf2(c3.x, c3.y); cp[7]  = packf2(c3.z, c3.w);
        cp[8]  = packf2(c4.x, c4.y); cp[9]  = packf2(c4.z, c4.w);
        cp[10] = packf2(c5.x, c5.y); cp[11] = packf2(c5.z, c5.w);
#pragma unroll
        for (int t = 0; t < TT; t++) {
            const ulonglong2* tz = (const ulonglong2*)tok[t];
            ulonglong2 z0 = tz[0], z1 = tz[1], z2 = tz[2];
            unsigned long long acc = ffma2(cp[0], z0.x, 0ull);
            acc = ffma2(cp[1], z0.y, acc);
            acc = ffma2(cp[2], z1.x, acc);
            acc = ffma2(cp[3], z1.y, acc);
            acc = ffma2(cp[4], z2.x, acc);
            acc = ffma2(cp[5], z2.y, acc);
            ulonglong2 z3 = tz[3], z4 = tz[4], z5 = tz[5];
            acc = ffma2(cp[6], z3.x, acc);
            acc = ffma2(cp[7], z3.y, acc);
            acc = ffma2(cp[8], z4.x, acc);
            acc = ffma2(cp[9], z4.y, acc);
            acc = ffma2(cp[10], z5.x, acc);
            acc = ffma2(cp[11], z5.y, acc);
            float2 s2 = unpackf2(acc);
            float sim = s2.x + s2.y;
            if (sim > bestv[t]) { bestv[t] = sim; besti[t] = r; }
        }
    }

    unsigned long long p[TT];
#pragma unroll
    for (int t = 0; t < TT; t++)
        p[t] = ((unsigned long long)forder(bestv[t]) << 32) |
               (unsigned long long)((unsigned)~besti[t]);
#pragma unroll
    for (int t = 0; t < TT; t++) {
#pragma unroll
        for (int off = 16; off; off >>= 1) {
            unsigned long long o = __shfl_down_sync(0xFFFFFFFFu, p[t], off);
            if (o > p[t]) p[t] = o;
        }
    }
    int warp = tid >> 5, lane = tid & 31;
    if (lane == 0) {
#pragma unroll
        for (int t = 0; t < TT; t++) wred[warp][t] = p[t];
    }
    __syncthreads();
    if (tid < TT) {
        unsigned long long m = wred[0][tid];
#pragma unroll
        for (int w = 1; w < 8; w++) {
            unsigned long long v = wred[w][tid];
            if (v > m) m = v;
        }
        if (token0 + tid < N) atomicMax(&g_best[token0 + tid], m);
    }
}

// ---------------- gather + renorm + STE, emit index ----------------------
__global__ void finalize_kernel(const float* __restrict__ cb, int N,
                                float* __restrict__ out, int idx_off) {
    int n = blockIdx.x * blockDim.x + threadIdx.x;
    if (n >= N) return;
    unsigned long long p = g_best[n];
    unsigned row = ~((unsigned)(p & 0xFFFFFFFFull));
    out[idx_off + n] = (float)row;
    const float* c = cb + (size_t)row * EMB;
    float ss = 0.0f;
    for (int d = 0; d < EMB; d++) { float v = c[d]; ss += v * v; }
    float nrm = sqrtf(ss);
    for (int d = 0; d < EMB; d++) {
        float q = c[d] / nrm;
        float zf = g_rdown[n * EMB + d];
        g_zq[n * EMB + d] = zf + (q - zf);   // STE forward rounding, ulp-exact
    }
}

// ---------------- upsample + accumulate z_hat, subtract residual ---------
__global__ void upsample_kernel(int s, int h, float* __restrict__ zhat) {
    __shared__ float zt[16][16];
    __shared__ float tmp[16][16];
    int blk = blockIdx.x, tid = threadIdx.x;
    int b = blk / 24, d = blk % 24;
    if (tid < h * h) zt[tid / h][tid % h] = g_zq[(b * h * h + tid) * EMB + d];
    __syncthreads();
    float up;
    if (h == 16) {
        up = zt[tid >> 4][tid & 15];
    } else {
        if (tid < 16 * h) {
            int Y = tid / h, x = tid % h;
            float acc = 0.0f;
            for (int y = 0; y < h; y++) acc += g_wu[s][y][Y] * zt[y][x];
            tmp[Y][x] = acc;
        }
        __syncthreads();
        int Y = tid >> 4, X = tid & 15;
        float acc = 0.0f;
        for (int x = 0; x < h; x++) acc += g_wu[s][x][X] * tmp[Y][x];
        up = acc;
    }
    int g = blk * 256 + tid;
    zhat[g] += up;
    g_res[g] -= up;
}

// ---------------- launch ---------------------------------------------------
extern "C" void kernel_launch(void* const* d_in, const int* in_sizes, int n_in,
                              void* d_out, int out_size) {
    const float* z;
    const float* cb;
    if (in_sizes[0] == 12288) {
        z = (const float*)d_in[0];
        cb = (const float*)d_in[1];
    } else {
        z = (const float*)d_in[1];
        cb = (const float*)d_in[0];
    }
    float* out = (float*)d_out;

    init_kernel<<<1, 256>>>(z, out);

    static const int hs[10] = {1, 2, 3, 4, 5, 6, 8, 10, 13, 16};
    int off = 12288;
    for (int s = 0; s < 10; s++) {
        int h = hs[s];
        int N = 2 * h * h;
        downsample_kernel<<<48, 256>>>(s, h, N);
        int tiles = (N + TT - 1) / TT;
        int gx = 2048 / tiles;
        if (gx > 768) gx = 768;
        if (gx < 1) gx = 1;
        int rpb = (K_CB + gx - 1) / gx;
        scan_kernel<<<dim3(gx, tiles), 256>>>(cb, N, rpb);
        finalize_kernel<<<(N + 127) / 128, 128>>>(cb, N, out, off);
        upsample_kernel<<<48, 256>>>(s, h, out);
        off += N;
    }
}

// round 5
// speedup vs baseline: 1.0106x; 1.0075x over previous
#include <cuda_runtime.h>
#include <math.h>

#define K_CB 196560
#define EMB 24
#define TT 16

// ---------------- device scratch (static allocation only) ----------------
__device__ float g_res[12288];                 // residual [2][24][16][16]
__device__ float g_rdown[512 * EMB];           // downsampled tokens [N][24]
__device__ float g_zq[512 * EMB];              // quantized tokens (post-STE)
__device__ unsigned long long g_best[512];     // packed (orderable sim, ~idx)
__device__ float g_wd[10][16][16];             // down weights [s][inY][outy]
__device__ float g_wu[10][16][16];             // up   weights [s][iny][outY]

// ---------------- helpers ----------------
__device__ __forceinline__ unsigned int forder(float f) {
    unsigned int u = __float_as_uint(f);
    return (u & 0x80000000u) ? ~u : (u | 0x80000000u);
}

__device__ __forceinline__ unsigned long long ffma2(unsigned long long a,
                                                    unsigned long long b,
                                                    unsigned long long c) {
    unsigned long long d;
    asm("fma.rn.f32x2 %0, %1, %2, %3;" : "=l"(d) : "l"(a), "l"(b), "l"(c));
    return d;
}
__device__ __forceinline__ unsigned long long packf2(float lo, float hi) {
    unsigned long long r;
    asm("mov.b64 %0, {%1, %2};" : "=l"(r) : "f"(lo), "f"(hi));
    return r;
}
__device__ __forceinline__ float2 unpackf2(unsigned long long v) {
    float lo, hi;
    asm("mov.b64 {%0, %1}, %2;" : "=f"(lo), "=f"(hi) : "l"(v));
    return make_float2(lo, hi);
}

// Replicates jax.image.resize compute_weight_mat (triangle kernel,
// antialias=True, translation=0) for one output column o.
__device__ void compute_col(int in_size, int out_size, int o, float* wcol) {
    float inv_scale = (float)((double)in_size / (double)out_size);
    float kscale = fmaxf(inv_scale, 1.0f);
    float sample_f = ((float)o + 0.5f) * inv_scale - 0.5f;
    float total = 0.0f;
    for (int i = 0; i < in_size; ++i) {
        float x = fabsf(sample_f - (float)i) / kscale;
        float w = fmaxf(0.0f, 1.0f - x);
        wcol[i] = w;
        total += w;
    }
    bool ok = fabsf(total) > 1000.0f * 1.1920928955078125e-7f;
    float denom = (total != 0.0f) ? total : 1.0f;
    bool inr = (sample_f >= -0.5f) && (sample_f <= (float)in_size - 0.5f);
    for (int i = 0; i < in_size; ++i) {
        float w = ok ? (wcol[i] / denom) : 0.0f;
        wcol[i] = inr ? w : 0.0f;
    }
}

// ---------------- init: residual copy, zero z_hat, build weight mats ------
__global__ void init_kernel(const float* __restrict__ z, float* __restrict__ out) {
    int tid = threadIdx.x;
    for (int i = tid; i < 12288; i += blockDim.x) {
        g_res[i] = z[i];
        out[i] = 0.0f;
    }
    const int hs9[9] = {1, 2, 3, 4, 5, 6, 8, 10, 13};
    // 52 down-columns + 9*16 up-columns = 196 tasks
    for (int task = tid; task < 52 + 144; task += blockDim.x) {
        float wcol[16];
        if (task < 52) {
            int rem = task, s = 0;
            while (rem >= hs9[s]) { rem -= hs9[s]; s++; }
            compute_col(16, hs9[s], rem, wcol);
            for (int i = 0; i < 16; i++) g_wd[s][i][rem] = wcol[i];
        } else {
            int r = task - 52;
            int s = r / 16, o = r % 16;
            compute_col(hs9[s], 16, o, wcol);
            for (int i = 0; i < 16; i++) g_wu[s][i][o] = (i < hs9[s]) ? wcol[i] : 0.0f;
        }
    }
}

// ---------------- downsample residual -> tokens (separable H then W) ------
__global__ void downsample_kernel(int s, int h, int N) {
    __shared__ float tile[16][16];
    __shared__ float tmp[16][16];
    int blk = blockIdx.x;        // b*24 + d
    int tid = threadIdx.x;
    tile[tid >> 4][tid & 15] = g_res[blk * 256 + tid];
    if (blk == 0) {
        for (int n = tid; n < N; n += 256) g_best[n] = 0ull;
    }
    __syncthreads();
    int b = blk / 24, d = blk % 24;
    if (h == 16) {  // jax resize skips equal dims -> identity
        g_rdown[(b * 256 + tid) * EMB + d] = tile[tid >> 4][tid & 15];
        return;
    }
    if (tid < h * 16) {
        int y = tid / 16, X = tid % 16;
        float acc = 0.0f;
        for (int Y = 0; Y < 16; Y++) acc += g_wd[s][Y][y] * tile[Y][X];
        tmp[y][X] = acc;
    }
    __syncthreads();
    if (tid < h * h) {
        int y = tid / h, x = tid % h;
        float acc = 0.0f;
        for (int X = 0; X < 16; X++) acc += g_wd[s][X][x] * tmp[y][X];
        g_rdown[(b * h * h + tid) * EMB + d] = acc;
    }
}

// ---------------- the heavy scan: argmax over 196560 codewords ------------
__global__ void __launch_bounds__(256) scan_kernel(const float* __restrict__ cb,
                                                   int N, int rows_per_block) {
    __shared__ __align__(16) float tok[TT][24];
    __shared__ unsigned long long wred[8][TT];
    int tid = threadIdx.x;
    int token0 = blockIdx.y * TT;
    for (int i = tid; i < TT * 24; i += 256) {
        int t = i / 24, d = i % 24;
        int tk = token0 + t;
        tok[t][d] = (tk < N) ? g_rdown[tk * EMB + d] : 0.0f;
    }
    __syncthreads();

    float bestv[TT];
    int besti[TT];
#pragma unroll
    for (int t = 0; t < TT; t++) { bestv[t] = -3.4e38f; besti[t] = 0; }

    int rbeg = blockIdx.x * rows_per_block;
    int rend = min(K_CB, rbeg + rows_per_block);
    const float4* __restrict__ cbv = (const float4*)cb;

    for (int r = rbeg + tid; r < rend; r += 256) {
        float4 c0 = __ldg(&cbv[r * 6 + 0]);
        float4 c1 = __ldg(&cbv[r * 6 + 1]);
        float4 c2 = __ldg(&cbv[r * 6 + 2]);
        float4 c3 = __ldg(&cbv[r * 6 + 3]);
        float4 c4 = __ldg(&cbv[r * 6 + 4]);
        float4 c5 = __ldg(&cbv[r * 6 + 5]);
        unsigned long long cp[12];
        cp[0]  = packf2(c0.x, c0.y); cp[1]  = packf2(c0.z, c0.w);
        cp[2]  = packf2(c1.x, c1.y); cp[3]  = packf2(c1.z, c1.w);
        cp[4]  = packf2(c2.x, c2.y); cp[5]  = packf2(c2.z, c2.w);
        cp[6]  = packf2(c3.x, c3.y); cp[7]  = packf2(c3.z, c3.w);
        cp[8]  = packf2(c4.x, c4.y); cp[9]  = packf2(c4.z, c4.w);
        cp[10] = packf2(c5.x, c5.y); cp[11] = packf2(c5.z, c5.w);
#pragma unroll
        for (int t = 0; t < TT; t++) {
            const ulonglong2* tz = (const ulonglong2*)tok[t];
            ulonglong2 z0 = tz[0], z1 = tz[1], z2 = tz[2];
            unsigned long long acc = ffma2(cp[0], z0.x, 0ull);
            acc = ffma2(cp[1], z0.y, acc);
            acc = ffma2(cp[2], z1.x, acc);
            acc = ffma2(cp[3], z1.y, acc);
            acc = ffma2(cp[4], z2.x, acc);
            acc = ffma2(cp[5], z2.y, acc);
            ulonglong2 z3 = tz[3], z4 = tz[4], z5 = tz[5];
            acc = ffma2(cp[6], z3.x, acc);
            acc = ffma2(cp[7], z3.y, acc);
            acc = ffma2(cp[8], z4.x, acc);
            acc = ffma2(cp[9], z4.y, acc);
            acc = ffma2(cp[10], z5.x, acc);
            acc = ffma2(cp[11], z5.y, acc);
            float2 s2 = unpackf2(acc);
            float sim = s2.x + s2.y;
            if (sim > bestv[t]) { bestv[t] = sim; besti[t] = r; }
        }
    }

    unsigned long long p[TT];
#pragma unroll
    for (int t = 0; t < TT; t++)
        p[t] = ((unsigned long long)forder(bestv[t]) << 32) |
               (unsigned long long)((unsigned)~besti[t]);
#pragma unroll
    for (int t = 0; t < TT; t++) {
#pragma unroll
        for (int off = 16; off; off >>= 1) {
            unsigned long long o = __shfl_down_sync(0xFFFFFFFFu, p[t], off);
            if (o > p[t]) p[t] = o;
        }
    }
    int warp = tid >> 5, lane = tid & 31;
    if (lane == 0) {
#pragma unroll
        for (int t = 0; t < TT; t++) wred[warp][t] = p[t];
    }
    __syncthreads();
    if (tid < TT) {
        unsigned long long m = wred[0][tid];
#pragma unroll
        for (int w = 1; w < 8; w++) {
            unsigned long long v = wred[w][tid];
            if (v > m) m = v;
        }
        if (token0 + tid < N) atomicMax(&g_best[token0 + tid], m);
    }
}

// ---------------- gather + renorm + STE, emit index ----------------------
__global__ void finalize_kernel(const float* __restrict__ cb, int N,
                                float* __restrict__ out, int idx_off) {
    int n = blockIdx.x * blockDim.x + threadIdx.x;
    if (n >= N) return;
    unsigned long long p = g_best[n];
    unsigned row = ~((unsigned)(p & 0xFFFFFFFFull));
    out[idx_off + n] = (float)row;
    const float* c = cb + (size_t)row * EMB;
    float ss = 0.0f;
    for (int d = 0; d < EMB; d++) { float v = c[d]; ss += v * v; }
    float nrm = sqrtf(ss);
    for (int d = 0; d < EMB; d++) {
        float q = c[d] / nrm;
        float zf = g_rdown[n * EMB + d];
        g_zq[n * EMB + d] = zf + (q - zf);   // STE forward rounding, ulp-exact
    }
}

// ---------------- upsample + accumulate z_hat, subtract residual ---------
__global__ void upsample_kernel(int s, int h, float* __restrict__ zhat) {
    __shared__ float zt[16][16];
    __shared__ float tmp[16][16];
    int blk = blockIdx.x, tid = threadIdx.x;
    int b = blk / 24, d = blk % 24;
    if (tid < h * h) zt[tid / h][tid % h] = g_zq[(b * h * h + tid) * EMB + d];
    __syncthreads();
    float up;
    if (h == 16) {
        up = zt[tid >> 4][tid & 15];
    } else {
        if (tid < 16 * h) {
            int Y = tid / h, x = tid % h;
            float acc = 0.0f;
            for (int y = 0; y < h; y++) acc += g_wu[s][y][Y] * zt[y][x];
            tmp[Y][x] = acc;
        }
        __syncthreads();
        int Y = tid >> 4, X = tid & 15;
        float acc = 0.0f;
        for (int x = 0; x < h; x++) acc += g_wu[s][x][X] * tmp[Y][x];
        up = acc;
    }
    int g = blk * 256 + tid;
    zhat[g] += up;
    g_res[g] -= up;
}

// ---------------- launch ---------------------------------------------------
extern "C" void kernel_launch(void* const* d_in, const int* in_sizes, int n_in,
                              void* d_out, int out_size) {
    const float* z;
    const float* cb;
    if (in_sizes[0] == 12288) {
        z = (const float*)d_in[0];
        cb = (const float*)d_in[1];
    } else {
        z = (const float*)d_in[1];
        cb = (const float*)d_in[0];
    }
    float* out = (float*)d_out;

    init_kernel<<<1, 256>>>(z, out);

    static const int hs[10] = {1, 2, 3, 4, 5, 6, 8, 10, 13, 16};
    int off = 12288;
    for (int s = 0; s < 10; s++) {
        int h = hs[s];
        int N = 2 * h * h;
        downsample_kernel<<<48, 256>>>(s, h, N);
        int tiles = (N + TT - 1) / TT;
        int gx = 2048 / tiles;
        if (gx > 768) gx = 768;
        if (gx < 1) gx = 1;
        int rpb = (K_CB + gx - 1) / gx;
        scan_kernel<<<dim3(gx, tiles), 256>>>(cb, N, rpb);
        finalize_kernel<<<(N + 127) / 128, 128>>>(cb, N, out, off);
        upsample_kernel<<<48, 256>>>(s, h, out);
        off += N;
    }
}

// round 6
// speedup vs baseline: 1.1624x; 1.1502x over previous
#include <cuda_runtime.h>
#include <math.h>

#define K_CB 196560
#define EMB 24
#define TT 16

// ---------------- device scratch (static allocation only) ----------------
__device__ float g_res[12288];                 // residual [2][24][16][16]
__device__ float g_rdown[512 * EMB];           // downsampled tokens [N][24]
__device__ float g_zq[512 * EMB];              // quantized tokens (post-STE)
__device__ unsigned long long g_best[512];     // packed (orderable sim, ~idx)
__device__ float g_wd[10][16][16];             // down weights [s][inY][outy]
__device__ float g_wu[10][16][16];             // up   weights [s][iny][outY]
__device__ int g_cnt[10];                      // scan completion counters

// ---------------- helpers ----------------
__device__ __forceinline__ unsigned int forder(float f) {
    unsigned int u = __float_as_uint(f);
    return (u & 0x80000000u) ? ~u : (u | 0x80000000u);
}

__device__ __forceinline__ unsigned long long ffma2(unsigned long long a,
                                                    unsigned long long b,
                                                    unsigned long long c) {
    unsigned long long d;
    asm("fma.rn.f32x2 %0, %1, %2, %3;" : "=l"(d) : "l"(a), "l"(b), "l"(c));
    return d;
}
__device__ __forceinline__ float2 unpackf2(unsigned long long v) {
    float lo, hi;
    asm("mov.b64 {%0, %1}, %2;" : "=f"(lo), "=f"(hi) : "l"(v));
    return make_float2(lo, hi);
}

// Replicates jax.image.resize compute_weight_mat (triangle kernel,
// antialias=True, translation=0) for one output column o.
__device__ void compute_col(int in_size, int out_size, int o, float* wcol) {
    float inv_scale = (float)((double)in_size / (double)out_size);
    float kscale = fmaxf(inv_scale, 1.0f);
    float sample_f = ((float)o + 0.5f) * inv_scale - 0.5f;
    float total = 0.0f;
    for (int i = 0; i < in_size; ++i) {
        float x = fabsf(sample_f - (float)i) / kscale;
        float w = fmaxf(0.0f, 1.0f - x);
        wcol[i] = w;
        total += w;
    }
    bool ok = fabsf(total) > 1000.0f * 1.1920928955078125e-7f;
    float denom = (total != 0.0f) ? total : 1.0f;
    bool inr = (sample_f >= -0.5f) && (sample_f <= (float)in_size - 0.5f);
    for (int i = 0; i < in_size; ++i) {
        float w = ok ? (wcol[i] / denom) : 0.0f;
        wcol[i] = inr ? w : 0.0f;
    }
}

// --------- init: residual copy, zero z_hat, weights, scale-0 downsample ---
__global__ void init_kernel(const float* __restrict__ z, float* __restrict__ out) {
    __shared__ float tile[16][16];
    __shared__ float tmp[16][16];
    int tid = threadIdx.x;
    for (int i = tid; i < 12288; i += blockDim.x) {
        g_res[i] = z[i];
        out[i] = 0.0f;
    }
    if (tid < 10) g_cnt[tid] = 0;
    if (tid < 2) g_best[tid] = 0ull;   // scale 0 has N=2 tokens
    const int hs9[9] = {1, 2, 3, 4, 5, 6, 8, 10, 13};
    for (int task = tid; task < 52 + 144; task += blockDim.x) {
        float wcol[16];
        if (task < 52) {
            int rem = task, s = 0;
            while (rem >= hs9[s]) { rem -= hs9[s]; s++; }
            compute_col(16, hs9[s], rem, wcol);
            for (int i = 0; i < 16; i++) g_wd[s][i][rem] = wcol[i];
        } else {
            int r = task - 52;
            int s = r / 16, o = r % 16;
            compute_col(hs9[s], 16, o, wcol);
            for (int i = 0; i < 16; i++) g_wu[s][i][o] = (i < hs9[s]) ? wcol[i] : 0.0f;
        }
    }
    __syncthreads();
    // downsample scale 0 (h=1) for all 48 (b,d) planes, sequentially
    for (int blk = 0; blk < 48; blk++) {
        tile[tid >> 4][tid & 15] = g_res[blk * 256 + tid];
        __syncthreads();
        int b = blk / 24, d = blk % 24;
        if (tid < 16) {  // stage 1: y=0 only (h=1)
            int X = tid;
            float acc = 0.0f;
            for (int Y = 0; Y < 16; Y++) acc += g_wd[0][Y][0] * tile[Y][X];
            tmp[0][X] = acc;
        }
        __syncthreads();
        if (tid == 0) {
            float acc = 0.0f;
            for (int X = 0; X < 16; X++) acc += g_wd[0][X][0] * tmp[0][X];
            g_rdown[b * EMB + d] = acc;
        }
        __syncthreads();
    }
}

// ---------------- scan + fused finalize (last block) ----------------------
__global__ void __launch_bounds__(256, 2)
scan_kernel(const float* __restrict__ cb, int s, int N, int rpb, int nblocks,
            float* __restrict__ out, int idx_off) {
    __shared__ __align__(16) float tok[TT][24];
    __shared__ unsigned long long wred[8][TT];
    __shared__ int s_last;
    int tid = threadIdx.x;
    int token0 = blockIdx.y * TT;
    for (int i = tid; i < TT * 24; i += 256) {
        int t = i / 24, d = i % 24;
        int tk = token0 + t;
        tok[t][d] = (tk < N) ? g_rdown[tk * EMB + d] : 0.0f;
    }
    __syncthreads();

    float bestv[TT];
    int besti[TT];
#pragma unroll
    for (int t = 0; t < TT; t++) { bestv[t] = -3.4e38f; besti[t] = 0; }

    int rbeg = blockIdx.x * rpb;
    int rend = min(K_CB, rbeg + rpb);
    const ulonglong2* __restrict__ cbu = (const ulonglong2*)cb;

    for (int r = rbeg + tid; r < rend; r += 256) {
        const ulonglong2* p = cbu + (size_t)r * 6;
        ulonglong2 q0 = __ldg(p + 0), q1 = __ldg(p + 1), q2 = __ldg(p + 2);
        ulonglong2 q3 = __ldg(p + 3), q4 = __ldg(p + 4), q5 = __ldg(p + 5);
#pragma unroll
        for (int t = 0; t < TT; t++) {
            const ulonglong2* tz = (const ulonglong2*)tok[t];
            ulonglong2 z0 = tz[0], z1 = tz[1], z2 = tz[2];
            unsigned long long acc = ffma2(q0.x, z0.x, 0ull);
            acc = ffma2(q0.y, z0.y, acc);
            acc = ffma2(q1.x, z1.x, acc);
            acc = ffma2(q1.y, z1.y, acc);
            acc = ffma2(q2.x, z2.x, acc);
            acc = ffma2(q2.y, z2.y, acc);
            ulonglong2 z3 = tz[3], z4 = tz[4], z5 = tz[5];
            acc = ffma2(q3.x, z3.x, acc);
            acc = ffma2(q3.y, z3.y, acc);
            acc = ffma2(q4.x, z4.x, acc);
            acc = ffma2(q4.y, z4.y, acc);
            acc = ffma2(q5.x, z5.x, acc);
            acc = ffma2(q5.y, z5.y, acc);
            float2 s2 = unpackf2(acc);
            float sim = s2.x + s2.y;
            if (sim > bestv[t]) { bestv[t] = sim; besti[t] = r; }
        }
    }

    unsigned long long p[TT];
#pragma unroll
    for (int t = 0; t < TT; t++)
        p[t] = ((unsigned long long)forder(bestv[t]) << 32) |
               (unsigned long long)((unsigned)~besti[t]);
#pragma unroll
    for (int t = 0; t < TT; t++) {
#pragma unroll
        for (int off = 16; off; off >>= 1) {
            unsigned long long o = __shfl_down_sync(0xFFFFFFFFu, p[t], off);
            if (o > p[t]) p[t] = o;
        }
    }
    int warp = tid >> 5, lane = tid & 31;
    if (lane == 0) {
#pragma unroll
        for (int t = 0; t < TT; t++) wred[warp][t] = p[t];
    }
    __syncthreads();
    if (tid < TT) {
        unsigned long long m = wred[0][tid];
#pragma unroll
        for (int w = 1; w < 8; w++) {
            unsigned long long v = wred[w][tid];
            if (v > m) m = v;
        }
        if (token0 + tid < N) atomicMax(&g_best[token0 + tid], m);
    }

    // ---- last-block-done: fused finalize (gather + renorm + STE + index) --
    __threadfence();
    if (tid == 0) s_last = (atomicAdd(&g_cnt[s], 1) == nblocks - 1);
    __syncthreads();
    if (!s_last) return;
    __threadfence();
    for (int n = tid; n < N; n += 256) {
        unsigned long long pk = atomicAdd(&g_best[n], 0ull);  // L2-coherent read
        unsigned row = ~((unsigned)(pk & 0xFFFFFFFFull));
        out[idx_off + n] = (float)row;
        const float* c = cb + (size_t)row * EMB;
        float ss = 0.0f;
        for (int d = 0; d < EMB; d++) { float v = c[d]; ss += v * v; }
        float nrm = sqrtf(ss);
        for (int d = 0; d < EMB; d++) {
            float q = c[d] / nrm;
            float zf = g_rdown[n * EMB + d];
            g_zq[n * EMB + d] = zf + (q - zf);   // STE rounding, ulp-exact
        }
    }
}

// -------- fused: upsample + zhat/res update + downsample next scale -------
__global__ void updown_kernel(int s, int h, int hn, int Nn,
                              float* __restrict__ zhat) {
    __shared__ float zt[16][16];
    __shared__ float tmp[16][16];
    __shared__ float nres[16][16];
    int blk = blockIdx.x, tid = threadIdx.x;
    int b = blk / 24, d = blk % 24;
    if (tid < h * h) zt[tid / h][tid % h] = g_zq[(b * h * h + tid) * EMB + d];
    __syncthreads();
    float up;
    if (h == 16) {
        up = zt[tid >> 4][tid & 15];
    } else {
        if (tid < 16 * h) {
            int Y = tid / h, x = tid % h;
            float acc = 0.0f;
            for (int y = 0; y < h; y++) acc += g_wu[s][y][Y] * zt[y][x];
            tmp[Y][x] = acc;
        }
        __syncthreads();
        int Y = tid >> 4, X = tid & 15;
        float acc = 0.0f;
        for (int x = 0; x < h; x++) acc += g_wu[s][x][X] * tmp[Y][x];
        up = acc;
    }
    int g = blk * 256 + tid;
    zhat[g] += up;
    float nr = g_res[g] - up;
    g_res[g] = nr;

    if (hn <= 0) return;
    nres[tid >> 4][tid & 15] = nr;
    if (blk == 0) {
        for (int n = tid; n < Nn; n += 256) g_best[n] = 0ull;
    }
    __syncthreads();   // tmp reuse + nres ready
    int sn = s + 1;
    if (hn == 16) {    // jax resize skips equal dims -> identity
        g_rdown[(b * 256 + tid) * EMB + d] = nr;
        return;
    }
    if (tid < hn * 16) {
        int y = tid / 16, X = tid % 16;
        float acc = 0.0f;
        for (int Y = 0; Y < 16; Y++) acc += g_wd[sn][Y][y] * nres[Y][X];
        tmp[y][X] = acc;
    }
    __syncthreads();
    if (tid < hn * hn) {
        int y = tid / hn, x = tid % hn;
        float acc = 0.0f;
        for (int X = 0; X < 16; X++) acc += g_wd[sn][X][x] * tmp[y][X];
        g_rdown[(b * hn * hn + tid) * EMB + d] = acc;
    }
}

// ---------------- launch ---------------------------------------------------
extern "C" void kernel_launch(void* const* d_in, const int* in_sizes, int n_in,
                              void* d_out, int out_size) {
    const float* z;
    const float* cb;
    if (in_sizes[0] == 12288) {
        z = (const float*)d_in[0];
        cb = (const float*)d_in[1];
    } else {
        z = (const float*)d_in[1];
        cb = (const float*)d_in[0];
    }
    float* out = (float*)d_out;

    init_kernel<<<1, 256>>>(z, out);

    static const int hs[10] = {1, 2, 3, 4, 5, 6, 8, 10, 13, 16};
    int off = 12288;
    for (int s = 0; s < 10; s++) {
        int h = hs[s];
        int N = 2 * h * h;
        int tiles = (N + TT - 1) / TT;
        int gx = 296 / tiles;          // one full wave at 2 blocks/SM
        if (gx < 1) gx = 1;
        int rpb = (K_CB + gx - 1) / gx;
        scan_kernel<<<dim3(gx, tiles), 256>>>(cb, s, N, rpb, gx * tiles, out, off);
        int hn = (s < 9) ? hs[s + 1] : -1;
        int Nn = (s < 9) ? 2 * hn * hn : 0;
        updown_kernel<<<48, 256>>>(s, h, hn, Nn, out);
        off += N;
    }
}

// round 7
// speedup vs baseline: 1.2807x; 1.1017x over previous
#include <cuda_runtime.h>
#include <math.h>

#define K_CB 196560
#define EMB 24
#define TT 16
#define NBARS_TOTAL 22

// ---------------- device scratch (static allocation only) ----------------
__device__ float g_res[12288];                   // residual [2][24][16][16]
__device__ float g_rdown[512 * EMB];             // downsampled tokens [N][24]
__device__ float g_zq[512 * EMB];                // quantized tokens (post-STE)
__device__ unsigned long long g_bestbuf[2][512]; // double-buffered (sim,~idx)
__device__ float g_wd[10][16][16];               // down weights
__device__ float g_wu[10][16][16];               // up weights
__device__ int g_barcnt;                         // grid barrier arrivals
__device__ int g_bargen;                         // grid barrier generation

__constant__ int c_hs[10] = {1, 2, 3, 4, 5, 6, 8, 10, 13, 16};

// ---------------- helpers ----------------
__device__ __forceinline__ unsigned int forder(float f) {
    unsigned int u = __float_as_uint(f);
    return (u & 0x80000000u) ? ~u : (u | 0x80000000u);
}
__device__ __forceinline__ unsigned long long ffma2(unsigned long long a,
                                                    unsigned long long b,
                                                    unsigned long long c) {
    unsigned long long d;
    asm("fma.rn.f32x2 %0, %1, %2, %3;" : "=l"(d) : "l"(a), "l"(b), "l"(c));
    return d;
}
__device__ __forceinline__ float2 unpackf2(unsigned long long v) {
    float lo, hi;
    asm("mov.b64 {%0, %1}, %2;" : "=f"(lo), "=f"(hi) : "l"(v));
    return make_float2(lo, hi);
}

// jax.image.resize compute_weight_mat (triangle kernel, antialias, tr=0)
__device__ void compute_col(int in_size, int out_size, int o, float* wcol) {
    float inv_scale = (float)((double)in_size / (double)out_size);
    float kscale = fmaxf(inv_scale, 1.0f);
    float sample_f = ((float)o + 0.5f) * inv_scale - 0.5f;
    float total = 0.0f;
    for (int i = 0; i < in_size; ++i) {
        float x = fabsf(sample_f - (float)i) / kscale;
        float w = fmaxf(0.0f, 1.0f - x);
        wcol[i] = w;
        total += w;
    }
    bool ok = fabsf(total) > 1000.0f * 1.1920928955078125e-7f;
    float denom = (total != 0.0f) ? total : 1.0f;
    bool inr = (sample_f >= -0.5f) && (sample_f <= (float)in_size - 0.5f);
    for (int i = 0; i < in_size; ++i) {
        float w = ok ? (wcol[i] / denom) : 0.0f;
        wcol[i] = inr ? w : 0.0f;
    }
}

// generation-counter grid barrier; gen is a per-thread local tracker
__device__ __forceinline__ void grid_barrier(int& gen) {
    __syncthreads();
    if (threadIdx.x == 0) {
        __threadfence();
        if (atomicAdd(&g_barcnt, 1) == (int)gridDim.x - 1) {
            atomicExch(&g_barcnt, 0);
            __threadfence();
            atomicAdd(&g_bargen, 1);
        } else {
            while (atomicAdd(&g_bargen, 0) < gen + 1) __nanosleep(64);
        }
        __threadfence();
    }
    gen++;
    __syncthreads();
}

// ---------------- the whole algorithm in one persistent kernel -----------
__global__ void __launch_bounds__(256, 2)
fused_kernel(const float* __restrict__ z, const float* __restrict__ cb,
             float* __restrict__ out) {
    __shared__ __align__(16) float s_tok[TT][24];
    __shared__ unsigned long long s_wred[8][TT];
    __shared__ float s_a[16][16];
    __shared__ float s_b[16][16];
    __shared__ float s_c[16][16];
    __shared__ int s_base;

    int tid = threadIdx.x;
    int blk = blockIdx.x;
    int NB = gridDim.x;

    // per-run barrier base (replay-safe: g_bargen advances exactly
    // NBARS_TOTAL per run; all entry reads happen before first release)
    if (tid == 0) {
        int g = atomicAdd(&g_bargen, 0);
        s_base = (g / NBARS_TOTAL) * NBARS_TOTAL;
    }
    __syncthreads();
    int gen = s_base;

    // ---- phase 0: copy residual, zero z_hat, weights, zero best bufs ----
    if (blk < 48) {
        g_res[blk * 256 + tid] = z[blk * 256 + tid];
        out[blk * 256 + tid] = 0.0f;
    } else if (blk < 48 + 196) {
        if (tid == 0) {
            const int hs9[9] = {1, 2, 3, 4, 5, 6, 8, 10, 13};
            int task = blk - 48;
            float wcol[16];
            if (task < 52) {
                int rem = task, s = 0;
                while (rem >= hs9[s]) { rem -= hs9[s]; s++; }
                compute_col(16, hs9[s], rem, wcol);
                for (int i = 0; i < 16; i++) g_wd[s][i][rem] = wcol[i];
            } else {
                int r = task - 52;
                int s = r / 16, o = r % 16;
                compute_col(hs9[s], 16, o, wcol);
                for (int i = 0; i < 16; i++)
                    g_wu[s][i][o] = (i < hs9[s]) ? wcol[i] : 0.0f;
            }
        }
    } else if (blk == 244) {
        for (int i = tid; i < 1024; i += 256)
            ((unsigned long long*)g_bestbuf)[i] = 0ull;
    }
    grid_barrier(gen);

    // ---- scale-0 downsample (h=1), blocks 0..47, one (b,d) plane each ---
    if (blk < 48) {
        int b = blk / 24, d = blk % 24;
        s_a[tid >> 4][tid & 15] = g_res[blk * 256 + tid];
        __syncthreads();
        if (tid < 16) {
            float acc = 0.0f;
            for (int Y = 0; Y < 16; Y++) acc += g_wd[0][Y][0] * s_a[Y][tid];
            s_b[0][tid] = acc;
        }
        __syncthreads();
        if (tid == 0) {
            float acc = 0.0f;
            for (int X = 0; X < 16; X++) acc += g_wd[0][X][0] * s_b[0][X];
            g_rdown[b * EMB + d] = acc;
        }
    }
    grid_barrier(gen);

    // ---- 10 scales ----
    int off = 12288;
    for (int s = 0; s < 10; s++) {
        int h = c_hs[s];
        int N = 2 * h * h;
        int tiles = (N + TT - 1) / TT;
        int nsl = NB / tiles;
        int tile = blk % tiles;
        int slice = blk / tiles;
        unsigned long long* best = g_bestbuf[s & 1];

        // ================= scan =================
        if (slice < nsl) {
            int token0 = tile * TT;
            for (int i = tid; i < TT * 24; i += 256) {
                int t = i / 24, d = i % 24;
                int tk = token0 + t;
                s_tok[t][d] = (tk < N) ? __ldcg(&g_rdown[tk * EMB + d]) : 0.0f;
            }
            __syncthreads();

            float bestv[TT];
            int besti[TT];
#pragma unroll
            for (int t = 0; t < TT; t++) { bestv[t] = -3.4e38f; besti[t] = 0; }

            int rpb = (K_CB + nsl - 1) / nsl;
            int rbeg = slice * rpb;
            int rend = min(K_CB, rbeg + rpb);
            const ulonglong2* __restrict__ cbu = (const ulonglong2*)cb;

            int base = rbeg;
            for (; base + 512 <= rend; base += 512) {
                int rA = base + tid, rB = rA + 256;
                const ulonglong2* pA = cbu + (size_t)rA * 6;
                const ulonglong2* pB = cbu + (size_t)rB * 6;
                ulonglong2 a0 = __ldg(pA + 0), a1 = __ldg(pA + 1), a2 = __ldg(pA + 2);
                ulonglong2 a3 = __ldg(pA + 3), a4 = __ldg(pA + 4), a5 = __ldg(pA + 5);
                ulonglong2 b0 = __ldg(pB + 0), b1 = __ldg(pB + 1), b2 = __ldg(pB + 2);
                ulonglong2 b3 = __ldg(pB + 3), b4 = __ldg(pB + 4), b5 = __ldg(pB + 5);
#pragma unroll
                for (int t = 0; t < TT; t++) {
                    const ulonglong2* tz = (const ulonglong2*)s_tok[t];
                    ulonglong2 z0 = tz[0], z1 = tz[1], z2 = tz[2];
                    ulonglong2 z3 = tz[3], z4 = tz[4], z5 = tz[5];
                    unsigned long long accA = ffma2(a0.x, z0.x, 0ull);
                    unsigned long long accB = ffma2(b0.x, z0.x, 0ull);
                    accA = ffma2(a0.y, z0.y, accA); accB = ffma2(b0.y, z0.y, accB);
                    accA = ffma2(a1.x, z1.x, accA); accB = ffma2(b1.x, z1.x, accB);
                    accA = ffma2(a1.y, z1.y, accA); accB = ffma2(b1.y, z1.y, accB);
                    accA = ffma2(a2.x, z2.x, accA); accB = ffma2(b2.x, z2.x, accB);
                    accA = ffma2(a2.y, z2.y, accA); accB = ffma2(b2.y, z2.y, accB);
                    accA = ffma2(a3.x, z3.x, accA); accB = ffma2(b3.x, z3.x, accB);
                    accA = ffma2(a3.y, z3.y, accA); accB = ffma2(b3.y, z3.y, accB);
                    accA = ffma2(a4.x, z4.x, accA); accB = ffma2(b4.x, z4.x, accB);
                    accA = ffma2(a4.y, z4.y, accA); accB = ffma2(b4.y, z4.y, accB);
                    accA = ffma2(a5.x, z5.x, accA); accB = ffma2(b5.x, z5.x, accB);
                    accA = ffma2(a5.y, z5.y, accA); accB = ffma2(b5.y, z5.y, accB);
                    float2 fa = unpackf2(accA);
                    float2 fb = unpackf2(accB);
                    float simA = fa.x + fa.y;
                    float simB = fb.x + fb.y;
                    if (simA > bestv[t]) { bestv[t] = simA; besti[t] = rA; }
                    if (simB > bestv[t]) { bestv[t] = simB; besti[t] = rB; }
                }
            }
            // tail: single rows
            for (int r = base + tid; r < rend; r += 256) {
                const ulonglong2* p = cbu + (size_t)r * 6;
                ulonglong2 q0 = __ldg(p + 0), q1 = __ldg(p + 1), q2 = __ldg(p + 2);
                ulonglong2 q3 = __ldg(p + 3), q4 = __ldg(p + 4), q5 = __ldg(p + 5);
#pragma unroll
                for (int t = 0; t < TT; t++) {
                    const ulonglong2* tz = (const ulonglong2*)s_tok[t];
                    ulonglong2 z0 = tz[0], z1 = tz[1], z2 = tz[2];
                    unsigned long long acc = ffma2(q0.x, z0.x, 0ull);
                    acc = ffma2(q0.y, z0.y, acc);
                    acc = ffma2(q1.x, z1.x, acc);
                    acc = ffma2(q1.y, z1.y, acc);
                    acc = ffma2(q2.x, z2.x, acc);
                    acc = ffma2(q2.y, z2.y, acc);
                    ulonglong2 z3 = tz[3], z4 = tz[4], z5 = tz[5];
                    acc = ffma2(q3.x, z3.x, acc);
                    acc = ffma2(q3.y, z3.y, acc);
                    acc = ffma2(q4.x, z4.x, acc);
                    acc = ffma2(q4.y, z4.y, acc);
                    acc = ffma2(q5.x, z5.x, acc);
                    acc = ffma2(q5.y, z5.y, acc);
                    float2 s2 = unpackf2(acc);
                    float sim = s2.x + s2.y;
                    if (sim > bestv[t]) { bestv[t] = sim; besti[t] = r; }
                }
            }

            unsigned long long pk[TT];
#pragma unroll
            for (int t = 0; t < TT; t++)
                pk[t] = ((unsigned long long)forder(bestv[t]) << 32) |
                        (unsigned long long)((unsigned)~besti[t]);
#pragma unroll
            for (int t = 0; t < TT; t++) {
#pragma unroll
                for (int o2 = 16; o2; o2 >>= 1) {
                    unsigned long long o = __shfl_down_sync(0xFFFFFFFFu, pk[t], o2);
                    if (o > pk[t]) pk[t] = o;
                }
            }
            int warp = tid >> 5, lane = tid & 31;
            if (lane == 0) {
#pragma unroll
                for (int t = 0; t < TT; t++) s_wred[warp][t] = pk[t];
            }
            __syncthreads();
            if (tid < TT) {
                unsigned long long m = s_wred[0][tid];
#pragma unroll
                for (int w = 1; w < 8; w++) {
                    unsigned long long v = s_wred[w][tid];
                    if (v > m) m = v;
                }
                if (token0 + tid < N) atomicMax(&best[token0 + tid], m);
            }
        }
        grid_barrier(gen);

        // ============ finalize (redundant per block) + updown ============
        if (blk < 48) {
            // finalize all N tokens (identical values from every block)
            for (int n = tid; n < N; n += 256) {
                unsigned long long pkv = __ldcg(&best[n]);
                unsigned row = ~((unsigned)(pkv & 0xFFFFFFFFull));
                out[off + n] = (float)row;
                const float* c = cb + (size_t)row * EMB;
                float ss = 0.0f;
                for (int d = 0; d < EMB; d++) { float v = c[d]; ss += v * v; }
                float nrm = sqrtf(ss);
                for (int d = 0; d < EMB; d++) {
                    float q = c[d] / nrm;
                    float zf = __ldcg(&g_rdown[n * EMB + d]);
                    g_zq[n * EMB + d] = zf + (q - zf);  // STE rounding
                }
            }
            __syncthreads();
            // updown own plane
            int b = blk / 24, d = blk % 24;
            if (tid < h * h) s_a[tid / h][tid % h] = g_zq[(b * h * h + tid) * EMB + d];
            __syncthreads();
            float up;
            if (h == 16) {
                up = s_a[tid >> 4][tid & 15];
            } else {
                if (tid < 16 * h) {
                    int Y = tid / h, x = tid % h;
                    float acc = 0.0f;
                    for (int y = 0; y < h; y++) acc += g_wu[s][y][Y] * s_a[y][x];
                    s_b[Y][x] = acc;
                }
                __syncthreads();
                int Y = tid >> 4, X = tid & 15;
                float acc = 0.0f;
                for (int x = 0; x < h; x++) acc += g_wu[s][x][X] * s_b[Y][x];
                up = acc;
            }
            int g = blk * 256 + tid;
            out[g] += up;
            float nr = g_res[g] - up;
            g_res[g] = nr;

            if (s < 9) {
                int hn = c_hs[s + 1];
                s_c[tid >> 4][tid & 15] = nr;
                __syncthreads();
                if (hn == 16) {  // jax resize skips equal dims -> identity
                    g_rdown[(b * 256 + tid) * EMB + d] = nr;
                } else {
                    if (tid < hn * 16) {
                        int y = tid / 16, X = tid % 16;
                        float acc = 0.0f;
                        for (int Y = 0; Y < 16; Y++)
                            acc += g_wd[s + 1][Y][y] * s_c[Y][X];
                        s_b[y][X] = acc;
                    }
                    __syncthreads();
                    if (tid < hn * hn) {
                        int y = tid / hn, x = tid % hn;
                        float acc = 0.0f;
                        for (int X = 0; X < 16; X++)
                            acc += g_wd[s + 1][X][x] * s_b[y][X];
                        g_rdown[(b * hn * hn + tid) * EMB + d] = acc;
                    }
                }
            }
        } else if (blk == 48 && s < 9) {
            unsigned long long* nxt = g_bestbuf[(s + 1) & 1];
            for (int n = tid; n < 512; n += 256) nxt[n] = 0ull;
        }
        grid_barrier(gen);
        off += N;
    }
}

// ---------------- launch ---------------------------------------------------
extern "C" void kernel_launch(void* const* d_in, const int* in_sizes, int n_in,
                              void* d_out, int out_size) {
    const float* z;
    const float* cb;
    if (in_sizes[0] == 12288) {
        z = (const float*)d_in[0];
        cb = (const float*)d_in[1];
    } else {
        z = (const float*)d_in[1];
        cb = (const float*)d_in[0];
    }
    float* out = (float*)d_out;

    int dev = 0, nsm = 148;
    cudaGetDevice(&dev);
    cudaDeviceGetAttribute(&nsm, cudaDevAttrMultiProcessorCount, dev);

    fused_kernel<<<nsm * 2, 256>>>(z, cb, out);
}